// round 15
// baseline (speedup 1.0000x reference)
#include <cuda_runtime.h>
#include <math.h>
#include <stdint.h>

// ---------------------------------------------------------------------------
// STGNN R15 (= R14 + bit-interleaved xsp layout: Gram A AND B fragment LDS
//            conflict-free; bit-identical numerics):
//  k0_prepG : Gcat[192][192] = stack_k(F_k @ w_ih^T)
//  k0b_pack : Gcat -> B-fragment table (tf32) + folded bias
//  k1_fused : sq -> Gram(3xtf32, d2' fused) -> bottom8(d2') parallel select
//             -> exp(8/row) -> sparse Cheb -> gi GEMM (mma tf32)
//  k2b_gru  : tensor-core GRU, fused FC
//  k3_fc    : final reduce
// ---------------------------------------------------------------------------

#define DEV static __device__ __forceinline__
typedef unsigned long long ull;

// device scratch (no allocations allowed)
__device__ float g_gi[524288ull * 192];  // gi fragments: [(st*32+l)*24+nt][lane][4]
__device__ float g_G[192 * 192];         // Gcat
__device__ float g_Gf[24 * 24 * 32 * 2]; // B fragments: [kk][nt][lane]{2} tf32 bits
__device__ float g_bias[192];            // b_ih + b_hh (cols<128)
__device__ float g_part[1024];           // per-warp FC partials

DEV uint32_t to_tf32(float f) {
    uint32_t r;
    asm("cvt.rna.tf32.f32 %0, %1;" : "=r"(r) : "f"(f));
    return r;
}

DEV void mma8(float* c, const uint32_t* a, const uint32_t* b) {
    asm volatile(
        "mma.sync.aligned.m16n8k8.row.col.f32.tf32.tf32.f32 "
        "{%0,%1,%2,%3}, {%4,%5,%6,%7}, {%8,%9}, {%0,%1,%2,%3};"
        : "+f"(c[0]), "+f"(c[1]), "+f"(c[2]), "+f"(c[3])
        : "r"(a[0]), "r"(a[1]), "r"(a[2]), "r"(a[3]), "r"(b[0]), "r"(b[1]));
}

// keep 8 smallest, sorted ascending
DEV void ins8min(float (&lk)[8], float v) {
#pragma unroll
    for (int i = 0; i < 8; i++) {
        float lo = fminf(lk[i], v);
        v = fmaxf(lk[i], v);
        lk[i] = lo;
    }
}

// bit-interleaved x layout: bank = 4*(n&7) + (f&3) -> fragment loads
// (rows ..+g, cols ..+tg) are conflict-free for both A and B operands.
DEV int XI(int n, int f) {
    return (((n >> 3) << 4) + (f >> 2)) * 32 + ((n & 7) << 2) + (f & 3);
}

// ---------------------------------------------------------------------------
// k0: Gcat[(k*64+f)][j] = sum_h F[k][f][h] * w_ih[j][h].  grid=3, block=192.
// ---------------------------------------------------------------------------
__global__ void __launch_bounds__(192) k0_prepG(const float* __restrict__ filters,
                                                const float* __restrict__ w_ih) {
    __shared__ float Fs[4096];
    const int k = blockIdx.x, j = threadIdx.x;
    for (int i = j; i < 4096; i += 192) Fs[i] = filters[k * 4096 + i];
    float w[64];
#pragma unroll
    for (int h = 0; h < 64; h++) w[h] = w_ih[j * 64 + h];
    __syncthreads();
    for (int f = 0; f < 64; f++) {
        float s = 0.f;
#pragma unroll
        for (int h = 0; h < 64; h++) s = fmaf(Fs[f * 64 + h], w[h], s);
        g_G[(k * 64 + f) * 192 + j] = s;
    }
}

// ---------------------------------------------------------------------------
// k0b: pack Gcat into mma B-fragment layout + folded bias. grid=24, block=256.
// ---------------------------------------------------------------------------
__global__ void __launch_bounds__(256) k0b_pack(const float* __restrict__ b_ih,
                                                const float* __restrict__ b_hh) {
    const int tid = threadIdx.x, kk = blockIdx.x;
    if (kk == 0 && tid < 192)
        g_bias[tid] = b_ih[tid] + (tid < 128 ? b_hh[tid] : 0.f);
    for (int i = tid; i < 768; i += 256) {
        int nt = i >> 5, lid = i & 31;
        int g = lid >> 2, tg = lid & 3;
        float v0 = g_G[(kk * 8 + tg) * 192 + nt * 8 + g];
        float v1 = g_G[(kk * 8 + tg + 4) * 192 + nt * 8 + g];
        g_Gf[((kk * 24 + nt) * 32 + lid) * 2]     = __uint_as_float(to_tf32(v0));
        g_Gf[((kk * 24 + nt) * 32 + lid) * 2 + 1] = __uint_as_float(to_tf32(v1));
    }
}

// ---------------------------------------------------------------------------
// k1_fused: grid=8192, block=256.
// smem layout (floats):
//   xsp 0..4096 (XI layout), adj 4096..8256 (stride 65), t1 8256..12608
//   (stride 68), t2 12608..16960 (stride 68), sq 16960..17024,
//   val 17024..17536, idx 17536..18048.  total 18048 floats = 72192 B
// ---------------------------------------------------------------------------
#define SMEM1 (18048 * 4)

__global__ void __launch_bounds__(256) k1_fused(const float* __restrict__ x) {
    extern __shared__ __align__(16) float sm1[];
    float* xsp = sm1;
    float* adj = sm1 + 4096;
    float* t1  = sm1 + 8256;
    float* t2  = sm1 + 12608;
    float* sq  = sm1 + 16960;
    float* val = sm1 + 17024;
    int*   idx = (int*)(sm1 + 17536);

    const int m = blockIdx.x;
    const int b = m >> 5, l = m & 31;
    const int tid = threadIdx.x;
    const int wid = tid >> 5, lid = tid & 31;
    const int g = lid >> 2, tg = lid & 3;

    // load xf[n][f] -> xsp (XI layout). v bits: [1:0]=f4_low, [4:2]=n_low,
    // [7:5]=n_high, [9:8]=f4_high.  8 rows x 4 lanes per warp: 64B-coalesced
    // global reads, 4-way STS.
    const float* xb = x + (size_t)b * 64 * 2048 + l * 64;
#pragma unroll
    for (int k = 0; k < 4; k++) {
        int v = tid + (k << 8);
        int n  = (((v >> 5) & 7) << 3) + ((v & 31) >> 2);
        int f4 = (((v >> 8) & 3) << 2) + (v & 3);
        float4 t = *(const float4*)(xb + (size_t)n * 2048 + f4 * 4);
        *(float4*)(xsp + XI(n, f4 * 4)) = t;
    }
    __syncthreads();

    // sq[n] = sum_f x[n][f]^2  (4 threads/row + shfl reduce)
    {
        const int row = tid >> 2, seg = tid & 3;
        float s = 0.f;
#pragma unroll
        for (int e = 0; e < 16; e += 4) {
            float4 v = *(const float4*)(xsp + XI(row, seg * 16 + e));
            s = fmaf(v.x, v.x, s);
            s = fmaf(v.y, v.y, s);
            s = fmaf(v.z, v.z, s);
            s = fmaf(v.w, v.w, s);
        }
        s += __shfl_xor_sync(0xffffffffu, s, 1);
        s += __shfl_xor_sync(0xffffffffu, s, 2);
        if (seg == 0) sq[row] = s;
    }
    __syncthreads();

    // Gram = xs @ xs^T via 3xtf32 split mma; d2' = max(d2,0) fused in epilogue
    {
        const int mt2 = wid >> 1, ntb = (wid & 1) * 4;
        float cacc[4][4];
#pragma unroll
        for (int t = 0; t < 4; t++)
#pragma unroll
            for (int q = 0; q < 4; q++) cacc[t][q] = 0.f;

#pragma unroll
        for (int kk = 0; kk < 8; kk++) {
            const int c0 = kk * 8 + tg, c1 = c0 + 4;
            const int r0 = mt2 * 16 + g, r1 = r0 + 8;
            float av[4] = {xsp[XI(r0, c0)], xsp[XI(r1, c0)],
                           xsp[XI(r0, c1)], xsp[XI(r1, c1)]};
            uint32_t ah[4], al[4];
#pragma unroll
            for (int q = 0; q < 4; q++) {
                ah[q] = to_tf32(av[q]);
                al[q] = to_tf32(av[q] - __uint_as_float(ah[q]));
            }
#pragma unroll
            for (int t = 0; t < 4; t++) {
                const int nr = (ntb + t) * 8 + g;
                float b0 = xsp[XI(nr, c0)], b1 = xsp[XI(nr, c1)];
                uint32_t bh[2], bl[2];
                bh[0] = to_tf32(b0); bl[0] = to_tf32(b0 - __uint_as_float(bh[0]));
                bh[1] = to_tf32(b1); bl[1] = to_tf32(b1 - __uint_as_float(bh[1]));
                mma8(cacc[t], ah, bl);
                mma8(cacc[t], al, bh);
                mma8(cacc[t], ah, bh);
            }
        }
        const int r0 = mt2 * 16 + g;
        const float sr0 = sq[r0], sr1 = sq[r0 + 8];
#pragma unroll
        for (int t = 0; t < 4; t++) {
            const int col = (ntb + t) * 8 + tg * 2;
            const float sc0 = sq[col], sc1 = sq[col + 1];
            adj[r0 * 65 + col]       = fmaxf(sr0 + sc0 - 2.f * cacc[t][0], 0.f);
            adj[r0 * 65 + col + 1]   = fmaxf(sr0 + sc1 - 2.f * cacc[t][1], 0.f);
            adj[(r0 + 8) * 65 + col] = fmaxf(sr1 + sc0 - 2.f * cacc[t][2], 0.f);
            adj[(r0 + 8) * 65 + col + 1] =
                fmaxf(sr1 + sc1 - 2.f * cacc[t][3], 0.f);
        }
    }
    __syncthreads();

    // bottom-8 of d2' per row (== top-8 of sim), parallel ordered selection.
    {
        const int row = tid >> 2, seg = tid & 3;
        const float* rowp = adj + row * 65;
        const int j0 = seg * 16;
        float lk[8];
#pragma unroll
        for (int i = 0; i < 8; i++) lk[i] = 3.4e38f;
#pragma unroll
        for (int j = 0; j < 16; j++) ins8min(lk, rowp[j0 + j]);
#pragma unroll
        for (int o = 1; o <= 2; o <<= 1) {
            float ot[8];
#pragma unroll
            for (int i = 0; i < 8; i++)
                ot[i] = __shfl_xor_sync(0xffffffffu, lk[i], o);
#pragma unroll
            for (int i = 0; i < 8; i++) ins8min(lk, ot[i]);
        }
        const float thr = lk[7];

        int clt = 0, ceq = 0;
#pragma unroll
        for (int j = 0; j < 16; j++) {
            float v = rowp[j0 + j];
            clt += (v < thr) ? 1 : 0;
            ceq += (v == thr) ? 1 : 0;
        }
        int ilt = clt, ieq = ceq;
#pragma unroll
        for (int o = 1; o < 4; o <<= 1) {
            int tl = __shfl_up_sync(0xffffffffu, ilt, o);
            int te = __shfl_up_sync(0xffffffffu, ieq, o);
            if (seg >= o) { ilt += tl; ieq += te; }
        }
        const int plt = ilt - clt, peq = ieq - ceq;
        const int tot_lt = __shfl_sync(0xffffffffu, ilt, lid | 3);
        const int rem = 8 - tot_lt;
        int tb = min(ceq, max(rem - peq, 0));
        int off = plt + min(peq, rem);
#pragma unroll
        for (int j = 0; j < 16; j++) {
            float v = rowp[j0 + j];
            bool take = (v < thr);
            if (v == thr && tb > 0) { take = true; tb--; }
            if (take) {
                val[row * 8 + off] = __expf(-v);
                idx[row * 8 + off] = j0 + j;
                off++;
            }
        }
    }
    __syncwarp();

    // sparse Cheb: 4 threads per row, 16 f-cols each. lv/lj -> registers.
    const int row = tid >> 2, f0 = (tid & 3) << 4;
    float lv[8];
    int lj[8];
#pragma unroll
    for (int i = 0; i < 8; i++) { lv[i] = val[row * 8 + i]; lj[i] = idx[row * 8 + i]; }

    float4 a4[4];
#pragma unroll
    for (int q = 0; q < 4; q++) a4[q] = make_float4(0.f, 0.f, 0.f, 0.f);
#pragma unroll
    for (int i = 0; i < 8; i++) {
        float v = lv[i];
#pragma unroll
        for (int q = 0; q < 4; q++) {
            float4 t = *(const float4*)(xsp + XI(lj[i], f0 + q * 4));
            a4[q].x = fmaf(v, t.x, a4[q].x);
            a4[q].y = fmaf(v, t.y, a4[q].y);
            a4[q].z = fmaf(v, t.z, a4[q].z);
            a4[q].w = fmaf(v, t.w, a4[q].w);
        }
    }
#pragma unroll
    for (int q = 0; q < 4; q++) *(float4*)(t1 + row * 68 + f0 + q * 4) = a4[q];
    __syncthreads();

    // Tx2 = 2*adj_sparse @ Tx1 - xs  -> t2
    float4 b4[4];
#pragma unroll
    for (int q = 0; q < 4; q++) b4[q] = make_float4(0.f, 0.f, 0.f, 0.f);
#pragma unroll
    for (int i = 0; i < 8; i++) {
        float v = lv[i];
        const float4* tr4 = (const float4*)(t1 + lj[i] * 68 + f0);
#pragma unroll
        for (int q = 0; q < 4; q++) {
            float4 t = tr4[q];
            b4[q].x = fmaf(v, t.x, b4[q].x);
            b4[q].y = fmaf(v, t.y, b4[q].y);
            b4[q].z = fmaf(v, t.z, b4[q].z);
            b4[q].w = fmaf(v, t.w, b4[q].w);
        }
    }
#pragma unroll
    for (int q = 0; q < 4; q++) {
        float4 xv = *(const float4*)(xsp + XI(row, f0 + q * 4));
        float4 tn;
        tn.x = 2.f * b4[q].x - xv.x;
        tn.y = 2.f * b4[q].y - xv.y;
        tn.z = 2.f * b4[q].z - xv.z;
        tn.w = 2.f * b4[q].w - xv.w;
        *(float4*)(t2 + row * 68 + f0 + q * 4) = tn;
    }
    __syncthreads();

    // ---- gi GEMM: gi = [xsp|t1|t2] @ Gcat + bias, mma tf32 ----
    const int mt = wid & 3, nh = wid >> 2;
    float acc[12][4];
#pragma unroll
    for (int nt = 0; nt < 12; nt++)
#pragma unroll
        for (int q = 0; q < 4; q++) acc[nt][q] = 0.f;

    const int r0 = mt * 16 + g;
#pragma unroll
    for (int kk = 0; kk < 24; kk++) {
        const int c0 = (kk & 7) * 8 + tg;
        uint32_t af[4];
        if (kk < 8) {
            af[0] = to_tf32(xsp[XI(r0, c0)]);
            af[1] = to_tf32(xsp[XI(r0 + 8, c0)]);
            af[2] = to_tf32(xsp[XI(r0, c0 + 4)]);
            af[3] = to_tf32(xsp[XI(r0 + 8, c0 + 4)]);
        } else {
            const float* Ab = (kk < 16) ? t1 : t2;
            af[0] = to_tf32(Ab[r0 * 68 + c0]);
            af[1] = to_tf32(Ab[(r0 + 8) * 68 + c0]);
            af[2] = to_tf32(Ab[r0 * 68 + c0 + 4]);
            af[3] = to_tf32(Ab[(r0 + 8) * 68 + c0 + 4]);
        }
        const float2* Bf = (const float2*)g_Gf + ((size_t)kk * 24 + nh * 12) * 32 + lid;
#pragma unroll
        for (int nt = 0; nt < 12; nt++) {
            float2 bv = Bf[(size_t)nt * 32];
            uint32_t bf2[2] = {__float_as_uint(bv.x), __float_as_uint(bv.y)};
            mma8(acc[nt], af, bf2);
        }
    }

    // epilogue: add bias, fragment-layout store
    const int st = b * 4 + mt;
    float4* dst = (float4*)g_gi + (((size_t)st * 32 + l) * 24 + nh * 12) * 32 + lid;
#pragma unroll
    for (int nt = 0; nt < 12; nt++) {
        const int ntg = nh * 12 + nt;
        float b0 = g_bias[ntg * 8 + tg * 2];
        float b1 = g_bias[ntg * 8 + tg * 2 + 1];
        dst[(size_t)nt * 32] = make_float4(acc[nt][0] + b0, acc[nt][1] + b1,
                                           acc[nt][2] + b0, acc[nt][3] + b1);
    }
}

// ---------------------------------------------------------------------------
// k2b: tensor-core GRU + fused FC. grid=256 blocks x 128 thr (4 warps).
// ---------------------------------------------------------------------------
#define SMEMB ((12288 + 4 * 1088) * 4)

DEV float sigf(float x) { return 1.f / (1.f + expf(-x)); }

__global__ void __launch_bounds__(128) k2b_gru(const float* __restrict__ w_hh,
                                               const float* __restrict__ b_hh,
                                               const float* __restrict__ fc_w) {
    extern __shared__ __align__(16) float smb[];
    float* pb  = smb;              // 12288: packed B frags (tf32 bits)
    float* hws = smb + 12288;      // 4*1088

    const int tid = threadIdx.x;
    const int ws = tid >> 5, lid = tid & 31;
    const int g = lid >> 2, tg = lid & 3;
    float* hw = hws + ws * 1088;

    for (int idx = tid; idx < 3072; idx += 128) {
        int kt = idx / 384, rem = idx % 384;
        int ntp = rem >> 5, l2 = rem & 31;
        int g2 = l2 >> 2, tg2 = l2 & 3;
        int k0 = kt * 8 + tg2;
        int n0 = (2 * ntp) * 8 + g2;
        int n1 = n0 + 8;
        float4 v;
        v.x = __uint_as_float(to_tf32(w_hh[n0 * 64 + k0]));
        v.y = __uint_as_float(to_tf32(w_hh[n0 * 64 + k0 + 4]));
        v.z = __uint_as_float(to_tf32(w_hh[n1 * 64 + k0]));
        v.w = __uint_as_float(to_tf32(w_hh[n1 * 64 + k0 + 4]));
        *(float4*)(pb + idx * 4) = v;
    }
    for (int i = tid; i < 4 * 1088; i += 128) hws[i] = 0.f;
    __syncthreads();

    const int st = blockIdx.x * 4 + ws;

    float bhn[8][2];
#pragma unroll
    for (int jt = 0; jt < 8; jt++) {
        bhn[jt][0] = b_hh[128 + jt * 8 + tg * 2];
        bhn[jt][1] = b_hh[128 + jt * 8 + tg * 2 + 1];
    }
    float hold[8][4];
#pragma unroll
    for (int jt = 0; jt < 8; jt++)
#pragma unroll
        for (int q = 0; q < 4; q++) hold[jt][q] = 0.f;

    const int sl = lid >> 1, ch = (lid & 1) * 32;
    const int n_g = (st * 16 + sl) & 63;
    const float* fwrow = fc_w + n_g * 2048 + ch;
    float fcacc = 0.f;

    const float4* gibase = (const float4*)g_gi + (size_t)st * 32 * 24 * 32 + lid;

    for (int l = 0; l < 32; l++) {
        float acc[24][4];
        const float4* gl = gibase + (size_t)l * 24 * 32;
#pragma unroll
        for (int nt = 0; nt < 16; nt++) {
            float4 t = gl[(size_t)nt * 32];
            acc[nt][0] = t.x; acc[nt][1] = t.y; acc[nt][2] = t.z; acc[nt][3] = t.w;
        }
        float4 gin[8];
#pragma unroll
        for (int jt = 0; jt < 8; jt++) gin[jt] = gl[(size_t)(16 + jt) * 32];
#pragma unroll
        for (int jt = 0; jt < 8; jt++) {
            acc[16 + jt][0] = bhn[jt][0]; acc[16 + jt][1] = bhn[jt][1];
            acc[16 + jt][2] = bhn[jt][0]; acc[16 + jt][3] = bhn[jt][1];
        }
        uint32_t af[8][4];
#pragma unroll
        for (int kt = 0; kt < 8; kt++) {
            int c0 = kt * 8 + tg;
            af[kt][0] = to_tf32(hw[g * 68 + c0]);
            af[kt][1] = to_tf32(hw[(g + 8) * 68 + c0]);
            af[kt][2] = to_tf32(hw[g * 68 + c0 + 4]);
            af[kt][3] = to_tf32(hw[(g + 8) * 68 + c0 + 4]);
        }
#pragma unroll
        for (int kt = 0; kt < 8; kt++) {
#pragma unroll
            for (int ntp = 0; ntp < 12; ntp++) {
                float4 bp = *(const float4*)(pb + (kt * 12 + ntp) * 128 + lid * 4);
                uint32_t b0[2] = {__float_as_uint(bp.x), __float_as_uint(bp.y)};
                uint32_t b1[2] = {__float_as_uint(bp.z), __float_as_uint(bp.w)};
                mma8(acc[ntp * 2], af[kt], b0);
                mma8(acc[ntp * 2 + 1], af[kt], b1);
            }
        }
        float hnew[8][4];
#pragma unroll
        for (int jt = 0; jt < 8; jt++) {
            float gq[4] = {gin[jt].x, gin[jt].y, gin[jt].z, gin[jt].w};
#pragma unroll
            for (int q = 0; q < 4; q++) {
                float r = sigf(acc[jt][q]);
                float z = sigf(acc[jt + 8][q]);
                float n = tanhf(gq[q] + r * acc[jt + 16][q]);
                float hv = (1.f - z) * n + z * hold[jt][q];
                hnew[jt][q] = hv;
                hold[jt][q] = hv;
            }
        }
        __syncwarp();
#pragma unroll
        for (int jt = 0; jt < 8; jt++) {
            *(float2*)(hw + g * 68 + jt * 8 + tg * 2) =
                make_float2(hnew[jt][0], hnew[jt][1]);
            *(float2*)(hw + (g + 8) * 68 + jt * 8 + tg * 2) =
                make_float2(hnew[jt][2], hnew[jt][3]);
        }
        __syncwarp();
        const float* hrow = hw + sl * 68 + ch;
        const float* fw = fwrow + l * 64;
#pragma unroll
        for (int u = 0; u < 8; u++) {
            float4 hh = *(const float4*)(hrow + u * 4);
            float4 wf = *(const float4*)(fw + u * 4);
            fcacc += hh.x * wf.x + hh.y * wf.y + hh.z * wf.z + hh.w * wf.w;
        }
    }

#pragma unroll
    for (int o = 16; o > 0; o >>= 1)
        fcacc += __shfl_down_sync(0xffffffffu, fcacc, o);
    if (lid == 0) g_part[blockIdx.x * 4 + ws] = fcacc;
}

// ---------------------------------------------------------------------------
__global__ void k3_fc(const float* __restrict__ fc_b, float* __restrict__ out) {
    int b = threadIdx.x;
    float s = fc_b[0];
#pragma unroll
    for (int k = 0; k < 4; k++) s += g_part[b * 4 + k];
    out[b] = s;
}

// ---------------------------------------------------------------------------
extern "C" void kernel_launch(void* const* d_in, const int* in_sizes, int n_in,
                              void* d_out, int out_size) {
    const float* x    = (const float*)d_in[0];
    const float* filt = (const float*)d_in[1];
    const float* w_ih = (const float*)d_in[2];
    const float* w_hh = (const float*)d_in[3];
    const float* b_ih = (const float*)d_in[4];
    const float* b_hh = (const float*)d_in[5];
    const float* fc_w = (const float*)d_in[6];
    const float* fc_b = (const float*)d_in[7];
    float* out = (float*)d_out;

    cudaFuncSetAttribute(k1_fused, cudaFuncAttributeMaxDynamicSharedMemorySize, SMEM1);
    cudaFuncSetAttribute(k2b_gru, cudaFuncAttributeMaxDynamicSharedMemorySize, SMEMB);

    k0_prepG<<<3, 192>>>(filt, w_ih);
    k0b_pack<<<24, 256>>>(b_ih, b_hh);
    k1_fused<<<8192, 256, SMEM1>>>(x);
    k2b_gru<<<256, 128, SMEMB>>>(w_hh, b_hh, fc_w);
    k3_fc<<<1, 256>>>(fc_b, out);
}

// round 16
// speedup vs baseline: 1.2245x; 1.2245x over previous
#include <cuda_runtime.h>
#include <math.h>
#include <stdint.h>

// ---------------------------------------------------------------------------
// STGNN R16 (= R14 + tanh-based sigmoid in k2b + registerized selection rows):
//  k0_prepG : Gcat[192][192] = stack_k(F_k @ w_ih^T)
//  k0b_pack : Gcat -> B-fragment table (tf32) + folded bias
//  k1_fused : sq -> Gram(3xtf32, d2' fused) -> bottom8(d2') parallel select
//             (row slice in registers) -> exp(8/row) -> sparse Cheb -> gi GEMM
//  k2b_gru  : tensor-core GRU (MUFU.TANH gates), fused FC
//  k3_fc    : final reduce
// ---------------------------------------------------------------------------

#define DEV static __device__ __forceinline__
typedef unsigned long long ull;

// device scratch (no allocations allowed)
__device__ float g_gi[524288ull * 192];  // gi fragments: [(st*32+l)*24+nt][lane][4]
__device__ float g_G[192 * 192];         // Gcat
__device__ float g_Gf[24 * 24 * 32 * 2]; // B fragments: [kk][nt][lane]{2} tf32 bits
__device__ float g_bias[192];            // b_ih + b_hh (cols<128)
__device__ float g_part[1024];           // per-warp FC partials

DEV uint32_t to_tf32(float f) {
    uint32_t r;
    asm("cvt.rna.tf32.f32 %0, %1;" : "=r"(r) : "f"(f));
    return r;
}

DEV void mma8(float* c, const uint32_t* a, const uint32_t* b) {
    asm volatile(
        "mma.sync.aligned.m16n8k8.row.col.f32.tf32.tf32.f32 "
        "{%0,%1,%2,%3}, {%4,%5,%6,%7}, {%8,%9}, {%0,%1,%2,%3};"
        : "+f"(c[0]), "+f"(c[1]), "+f"(c[2]), "+f"(c[3])
        : "r"(a[0]), "r"(a[1]), "r"(a[2]), "r"(a[3]), "r"(b[0]), "r"(b[1]));
}

// keep 8 smallest, sorted ascending
DEV void ins8min(float (&lk)[8], float v) {
#pragma unroll
    for (int i = 0; i < 8; i++) {
        float lo = fminf(lk[i], v);
        v = fmaxf(lk[i], v);
        lk[i] = lo;
    }
}

// ---------------------------------------------------------------------------
// k0: Gcat[(k*64+f)][j] = sum_h F[k][f][h] * w_ih[j][h].  grid=3, block=192.
// ---------------------------------------------------------------------------
__global__ void __launch_bounds__(192) k0_prepG(const float* __restrict__ filters,
                                                const float* __restrict__ w_ih) {
    __shared__ float Fs[4096];
    const int k = blockIdx.x, j = threadIdx.x;
    for (int i = j; i < 4096; i += 192) Fs[i] = filters[k * 4096 + i];
    float w[64];
#pragma unroll
    for (int h = 0; h < 64; h++) w[h] = w_ih[j * 64 + h];
    __syncthreads();
    for (int f = 0; f < 64; f++) {
        float s = 0.f;
#pragma unroll
        for (int h = 0; h < 64; h++) s = fmaf(Fs[f * 64 + h], w[h], s);
        g_G[(k * 64 + f) * 192 + j] = s;
    }
}

// ---------------------------------------------------------------------------
// k0b: pack Gcat into mma B-fragment layout + folded bias. grid=24, block=256.
// ---------------------------------------------------------------------------
__global__ void __launch_bounds__(256) k0b_pack(const float* __restrict__ b_ih,
                                                const float* __restrict__ b_hh) {
    const int tid = threadIdx.x, kk = blockIdx.x;
    if (kk == 0 && tid < 192)
        g_bias[tid] = b_ih[tid] + (tid < 128 ? b_hh[tid] : 0.f);
    for (int i = tid; i < 768; i += 256) {
        int nt = i >> 5, lid = i & 31;
        int g = lid >> 2, tg = lid & 3;
        float v0 = g_G[(kk * 8 + tg) * 192 + nt * 8 + g];
        float v1 = g_G[(kk * 8 + tg + 4) * 192 + nt * 8 + g];
        g_Gf[((kk * 24 + nt) * 32 + lid) * 2]     = __uint_as_float(to_tf32(v0));
        g_Gf[((kk * 24 + nt) * 32 + lid) * 2 + 1] = __uint_as_float(to_tf32(v1));
    }
}

// ---------------------------------------------------------------------------
// k1_fused: grid=8192, block=256.  (R9 smem layout, 73216 B)
//   xsp 0..4352 (stride 68), adj 4352..8512 (stride 65; holds d2'), t1
//   8512..12864, t2 12864..17216, sq 17216..17280, val 17280..17792,
//   idx 17792..18304
// ---------------------------------------------------------------------------
#define SMEM1 (18304 * 4)

__global__ void __launch_bounds__(256) k1_fused(const float* __restrict__ x) {
    extern __shared__ __align__(16) float sm1[];
    float* xsp = sm1;
    float* adj = sm1 + 4352;
    float* t1  = sm1 + 8512;
    float* t2  = sm1 + 12864;
    float* sq  = sm1 + 17216;
    float* val = sm1 + 17280;
    int*   idx = (int*)(sm1 + 17792);

    const int m = blockIdx.x;
    const int b = m >> 5, l = m & 31;
    const int tid = threadIdx.x;
    const int wid = tid >> 5, lid = tid & 31;
    const int g = lid >> 2, tg = lid & 3;

    // load xf[n][f] -> xsp (stride 68)
    const float* xb = x + (size_t)b * 64 * 2048 + l * 64;
#pragma unroll
    for (int k = 0; k < 4; k++) {
        int v = tid + k * 256;
        int n = v >> 4, fo = (v & 15) << 2;
        *(float4*)(xsp + n * 68 + fo) = *(const float4*)(xb + (size_t)n * 2048 + fo);
    }
    __syncthreads();

    // sq[n] = sum_f x[n][f]^2  (4 threads/row + shfl reduce)
    {
        const int row = tid >> 2, seg = tid & 3;
        const float* xr = xsp + row * 68 + seg * 16;
        float s = 0.f;
#pragma unroll
        for (int e = 0; e < 16; e += 4) {
            float4 v = *(const float4*)(xr + e);
            s = fmaf(v.x, v.x, s);
            s = fmaf(v.y, v.y, s);
            s = fmaf(v.z, v.z, s);
            s = fmaf(v.w, v.w, s);
        }
        s += __shfl_xor_sync(0xffffffffu, s, 1);
        s += __shfl_xor_sync(0xffffffffu, s, 2);
        if (seg == 0) sq[row] = s;
    }
    __syncthreads();

    // Gram = xs @ xs^T via 3xtf32 split mma; d2' = max(d2,0) fused in epilogue
    {
        const int mt2 = wid >> 1, ntb = (wid & 1) * 4;
        float cacc[4][4];
#pragma unroll
        for (int t = 0; t < 4; t++)
#pragma unroll
            for (int q = 0; q < 4; q++) cacc[t][q] = 0.f;

#pragma unroll
        for (int kk = 0; kk < 8; kk++) {
            const int c0 = kk * 8 + tg, c1 = c0 + 4;
            const int r0 = mt2 * 16 + g, r1 = r0 + 8;
            float av[4] = {xsp[r0 * 68 + c0], xsp[r1 * 68 + c0],
                           xsp[r0 * 68 + c1], xsp[r1 * 68 + c1]};
            uint32_t ah[4], al[4];
#pragma unroll
            for (int q = 0; q < 4; q++) {
                ah[q] = to_tf32(av[q]);
                al[q] = to_tf32(av[q] - __uint_as_float(ah[q]));
            }
#pragma unroll
            for (int t = 0; t < 4; t++) {
                const int nr = (ntb + t) * 8 + g;
                float b0 = xsp[nr * 68 + c0], b1 = xsp[nr * 68 + c1];
                uint32_t bh[2], bl[2];
                bh[0] = to_tf32(b0); bl[0] = to_tf32(b0 - __uint_as_float(bh[0]));
                bh[1] = to_tf32(b1); bl[1] = to_tf32(b1 - __uint_as_float(bh[1]));
                mma8(cacc[t], ah, bl);
                mma8(cacc[t], al, bh);
                mma8(cacc[t], ah, bh);
            }
        }
        const int r0 = mt2 * 16 + g;
        const float sr0 = sq[r0], sr1 = sq[r0 + 8];
#pragma unroll
        for (int t = 0; t < 4; t++) {
            const int col = (ntb + t) * 8 + tg * 2;
            const float sc0 = sq[col], sc1 = sq[col + 1];
            adj[r0 * 65 + col]       = fmaxf(sr0 + sc0 - 2.f * cacc[t][0], 0.f);
            adj[r0 * 65 + col + 1]   = fmaxf(sr0 + sc1 - 2.f * cacc[t][1], 0.f);
            adj[(r0 + 8) * 65 + col] = fmaxf(sr1 + sc0 - 2.f * cacc[t][2], 0.f);
            adj[(r0 + 8) * 65 + col + 1] =
                fmaxf(sr1 + sc1 - 2.f * cacc[t][3], 0.f);
        }
    }
    __syncthreads();

    // bottom-8 of d2' per row (== top-8 of sim), parallel ordered selection.
    // Row slice held in registers (one LDS pass instead of three).
    {
        const int row = tid >> 2, seg = tid & 3;
        const int j0 = seg * 16;
        float rv[16];
#pragma unroll
        for (int j = 0; j < 16; j++) rv[j] = adj[row * 65 + j0 + j];

        float lk[8];
#pragma unroll
        for (int i = 0; i < 8; i++) lk[i] = 3.4e38f;
#pragma unroll
        for (int j = 0; j < 16; j++) ins8min(lk, rv[j]);
#pragma unroll
        for (int o = 1; o <= 2; o <<= 1) {
            float ot[8];
#pragma unroll
            for (int i = 0; i < 8; i++)
                ot[i] = __shfl_xor_sync(0xffffffffu, lk[i], o);
#pragma unroll
            for (int i = 0; i < 8; i++) ins8min(lk, ot[i]);
        }
        const float thr = lk[7];

        int clt = 0, ceq = 0;
#pragma unroll
        for (int j = 0; j < 16; j++) {
            clt += (rv[j] < thr) ? 1 : 0;
            ceq += (rv[j] == thr) ? 1 : 0;
        }
        int ilt = clt, ieq = ceq;
#pragma unroll
        for (int o = 1; o < 4; o <<= 1) {
            int tl = __shfl_up_sync(0xffffffffu, ilt, o);
            int te = __shfl_up_sync(0xffffffffu, ieq, o);
            if (seg >= o) { ilt += tl; ieq += te; }
        }
        const int plt = ilt - clt, peq = ieq - ceq;
        const int tot_lt = __shfl_sync(0xffffffffu, ilt, lid | 3);
        const int rem = 8 - tot_lt;
        int tb = min(ceq, max(rem - peq, 0));
        int off = plt + min(peq, rem);
#pragma unroll
        for (int j = 0; j < 16; j++) {
            float v = rv[j];
            bool take = (v < thr);
            if (v == thr && tb > 0) { take = true; tb--; }
            if (take) {
                val[row * 8 + off] = __expf(-v);
                idx[row * 8 + off] = j0 + j;
                off++;
            }
        }
    }
    __syncwarp();

    // sparse Cheb: 4 threads per row, 16 f-cols each. lv/lj -> registers.
    const int row = tid >> 2, f0 = (tid & 3) << 4;
    float lv[8];
    int lj[8];
#pragma unroll
    for (int i = 0; i < 8; i++) { lv[i] = val[row * 8 + i]; lj[i] = idx[row * 8 + i]; }

    float4 a4[4];
#pragma unroll
    for (int q = 0; q < 4; q++) a4[q] = make_float4(0.f, 0.f, 0.f, 0.f);
#pragma unroll
    for (int i = 0; i < 8; i++) {
        float v = lv[i];
        const float4* xr = (const float4*)(xsp + lj[i] * 68 + f0);
#pragma unroll
        for (int q = 0; q < 4; q++) {
            float4 t = xr[q];
            a4[q].x = fmaf(v, t.x, a4[q].x);
            a4[q].y = fmaf(v, t.y, a4[q].y);
            a4[q].z = fmaf(v, t.z, a4[q].z);
            a4[q].w = fmaf(v, t.w, a4[q].w);
        }
    }
#pragma unroll
    for (int q = 0; q < 4; q++) *(float4*)(t1 + row * 68 + f0 + q * 4) = a4[q];
    __syncthreads();

    // Tx2 = 2*adj_sparse @ Tx1 - xs  -> t2
    float4 b4[4];
#pragma unroll
    for (int q = 0; q < 4; q++) b4[q] = make_float4(0.f, 0.f, 0.f, 0.f);
#pragma unroll
    for (int i = 0; i < 8; i++) {
        float v = lv[i];
        const float4* tr4 = (const float4*)(t1 + lj[i] * 68 + f0);
#pragma unroll
        for (int q = 0; q < 4; q++) {
            float4 t = tr4[q];
            b4[q].x = fmaf(v, t.x, b4[q].x);
            b4[q].y = fmaf(v, t.y, b4[q].y);
            b4[q].z = fmaf(v, t.z, b4[q].z);
            b4[q].w = fmaf(v, t.w, b4[q].w);
        }
    }
#pragma unroll
    for (int q = 0; q < 4; q++) {
        float4 xv = *(const float4*)(xsp + row * 68 + f0 + q * 4);
        float4 tn;
        tn.x = 2.f * b4[q].x - xv.x;
        tn.y = 2.f * b4[q].y - xv.y;
        tn.z = 2.f * b4[q].z - xv.z;
        tn.w = 2.f * b4[q].w - xv.w;
        *(float4*)(t2 + row * 68 + f0 + q * 4) = tn;
    }
    __syncthreads();

    // ---- gi GEMM: gi = [xsp|t1|t2] @ Gcat + bias, mma tf32 (R9 tiling) ----
    const int mt = wid & 3, nh = wid >> 2;
    float acc[12][4];
#pragma unroll
    for (int nt = 0; nt < 12; nt++)
#pragma unroll
        for (int q = 0; q < 4; q++) acc[nt][q] = 0.f;

    const int r0 = mt * 16 + g;
#pragma unroll
    for (int kk = 0; kk < 24; kk++) {
        const float* Abuf = (kk < 8) ? xsp : ((kk < 16) ? t1 : t2);
        const int c0 = (kk & 7) * 8 + tg;
        uint32_t af[4];
        af[0] = to_tf32(Abuf[r0 * 68 + c0]);
        af[1] = to_tf32(Abuf[(r0 + 8) * 68 + c0]);
        af[2] = to_tf32(Abuf[r0 * 68 + c0 + 4]);
        af[3] = to_tf32(Abuf[(r0 + 8) * 68 + c0 + 4]);
        const float2* Bf = (const float2*)g_Gf + ((size_t)kk * 24 + nh * 12) * 32 + lid;
#pragma unroll
        for (int nt = 0; nt < 12; nt++) {
            float2 bv = Bf[(size_t)nt * 32];
            uint32_t bf2[2] = {__float_as_uint(bv.x), __float_as_uint(bv.y)};
            mma8(acc[nt], af, bf2);
        }
    }

    // epilogue: add bias, fragment-layout store
    const int st = b * 4 + mt;
    float4* dst = (float4*)g_gi + (((size_t)st * 32 + l) * 24 + nh * 12) * 32 + lid;
#pragma unroll
    for (int nt = 0; nt < 12; nt++) {
        const int ntg = nh * 12 + nt;
        float b0 = g_bias[ntg * 8 + tg * 2];
        float b1 = g_bias[ntg * 8 + tg * 2 + 1];
        dst[(size_t)nt * 32] = make_float4(acc[nt][0] + b0, acc[nt][1] + b1,
                                           acc[nt][2] + b0, acc[nt][3] + b1);
    }
}

// ---------------------------------------------------------------------------
// k2b: tensor-core GRU + fused FC. grid=256 blocks x 128 thr (4 warps).
// Gates via MUFU.TANH only: sigma(x) = 0.5*tanh(x/2) + 0.5.
// ---------------------------------------------------------------------------
#define SMEMB ((12288 + 4 * 1088) * 4)

DEV float sigf(float x) { return fmaf(0.5f, tanhf(0.5f * x), 0.5f); }

__global__ void __launch_bounds__(128) k2b_gru(const float* __restrict__ w_hh,
                                               const float* __restrict__ b_hh,
                                               const float* __restrict__ fc_w) {
    extern __shared__ __align__(16) float smb[];
    float* pb  = smb;              // 12288: packed B frags (tf32 bits)
    float* hws = smb + 12288;      // 4*1088

    const int tid = threadIdx.x;
    const int ws = tid >> 5, lid = tid & 31;
    const int g = lid >> 2, tg = lid & 3;
    float* hw = hws + ws * 1088;

    for (int idx = tid; idx < 3072; idx += 128) {
        int kt = idx / 384, rem = idx % 384;
        int ntp = rem >> 5, l2 = rem & 31;
        int g2 = l2 >> 2, tg2 = l2 & 3;
        int k0 = kt * 8 + tg2;
        int n0 = (2 * ntp) * 8 + g2;
        int n1 = n0 + 8;
        float4 v;
        v.x = __uint_as_float(to_tf32(w_hh[n0 * 64 + k0]));
        v.y = __uint_as_float(to_tf32(w_hh[n0 * 64 + k0 + 4]));
        v.z = __uint_as_float(to_tf32(w_hh[n1 * 64 + k0]));
        v.w = __uint_as_float(to_tf32(w_hh[n1 * 64 + k0 + 4]));
        *(float4*)(pb + idx * 4) = v;
    }
    for (int i = tid; i < 4 * 1088; i += 128) hws[i] = 0.f;
    __syncthreads();

    const int st = blockIdx.x * 4 + ws;

    float bhn[8][2];
#pragma unroll
    for (int jt = 0; jt < 8; jt++) {
        bhn[jt][0] = b_hh[128 + jt * 8 + tg * 2];
        bhn[jt][1] = b_hh[128 + jt * 8 + tg * 2 + 1];
    }
    float hold[8][4];
#pragma unroll
    for (int jt = 0; jt < 8; jt++)
#pragma unroll
        for (int q = 0; q < 4; q++) hold[jt][q] = 0.f;

    const int sl = lid >> 1, ch = (lid & 1) * 32;
    const int n_g = (st * 16 + sl) & 63;
    const float* fwrow = fc_w + n_g * 2048 + ch;
    float fcacc = 0.f;

    const float4* gibase = (const float4*)g_gi + (size_t)st * 32 * 24 * 32 + lid;

    for (int l = 0; l < 32; l++) {
        float acc[24][4];
        const float4* gl = gibase + (size_t)l * 24 * 32;
#pragma unroll
        for (int nt = 0; nt < 16; nt++) {
            float4 t = gl[(size_t)nt * 32];
            acc[nt][0] = t.x; acc[nt][1] = t.y; acc[nt][2] = t.z; acc[nt][3] = t.w;
        }
        float4 gin[8];
#pragma unroll
        for (int jt = 0; jt < 8; jt++) gin[jt] = gl[(size_t)(16 + jt) * 32];
#pragma unroll
        for (int jt = 0; jt < 8; jt++) {
            acc[16 + jt][0] = bhn[jt][0]; acc[16 + jt][1] = bhn[jt][1];
            acc[16 + jt][2] = bhn[jt][0]; acc[16 + jt][3] = bhn[jt][1];
        }
        uint32_t af[8][4];
#pragma unroll
        for (int kt = 0; kt < 8; kt++) {
            int c0 = kt * 8 + tg;
            af[kt][0] = to_tf32(hw[g * 68 + c0]);
            af[kt][1] = to_tf32(hw[(g + 8) * 68 + c0]);
            af[kt][2] = to_tf32(hw[g * 68 + c0 + 4]);
            af[kt][3] = to_tf32(hw[(g + 8) * 68 + c0 + 4]);
        }
#pragma unroll
        for (int kt = 0; kt < 8; kt++) {
#pragma unroll
            for (int ntp = 0; ntp < 12; ntp++) {
                float4 bp = *(const float4*)(pb + (kt * 12 + ntp) * 128 + lid * 4);
                uint32_t b0[2] = {__float_as_uint(bp.x), __float_as_uint(bp.y)};
                uint32_t b1[2] = {__float_as_uint(bp.z), __float_as_uint(bp.w)};
                mma8(acc[ntp * 2], af[kt], b0);
                mma8(acc[ntp * 2 + 1], af[kt], b1);
            }
        }
        float hnew[8][4];
#pragma unroll
        for (int jt = 0; jt < 8; jt++) {
            float gq[4] = {gin[jt].x, gin[jt].y, gin[jt].z, gin[jt].w};
#pragma unroll
            for (int q = 0; q < 4; q++) {
                float r = sigf(acc[jt][q]);
                float z = sigf(acc[jt + 8][q]);
                float n = tanhf(gq[q] + r * acc[jt + 16][q]);
                float hv = (1.f - z) * n + z * hold[jt][q];
                hnew[jt][q] = hv;
                hold[jt][q] = hv;
            }
        }
        __syncwarp();
#pragma unroll
        for (int jt = 0; jt < 8; jt++) {
            *(float2*)(hw + g * 68 + jt * 8 + tg * 2) =
                make_float2(hnew[jt][0], hnew[jt][1]);
            *(float2*)(hw + (g + 8) * 68 + jt * 8 + tg * 2) =
                make_float2(hnew[jt][2], hnew[jt][3]);
        }
        __syncwarp();
        const float* hrow = hw + sl * 68 + ch;
        const float* fw = fwrow + l * 64;
#pragma unroll
        for (int u = 0; u < 8; u++) {
            float4 hh = *(const float4*)(hrow + u * 4);
            float4 wf = *(const float4*)(fw + u * 4);
            fcacc += hh.x * wf.x + hh.y * wf.y + hh.z * wf.z + hh.w * wf.w;
        }
    }

#pragma unroll
    for (int o = 16; o > 0; o >>= 1)
        fcacc += __shfl_down_sync(0xffffffffu, fcacc, o);
    if (lid == 0) g_part[blockIdx.x * 4 + ws] = fcacc;
}

// ---------------------------------------------------------------------------
__global__ void k3_fc(const float* __restrict__ fc_b, float* __restrict__ out) {
    int b = threadIdx.x;
    float s = fc_b[0];
#pragma unroll
    for (int k = 0; k < 4; k++) s += g_part[b * 4 + k];
    out[b] = s;
}

// ---------------------------------------------------------------------------
extern "C" void kernel_launch(void* const* d_in, const int* in_sizes, int n_in,
                              void* d_out, int out_size) {
    const float* x    = (const float*)d_in[0];
    const float* filt = (const float*)d_in[1];
    const float* w_ih = (const float*)d_in[2];
    const float* w_hh = (const float*)d_in[3];
    const float* b_ih = (const float*)d_in[4];
    const float* b_hh = (const float*)d_in[5];
    const float* fc_w = (const float*)d_in[6];
    const float* fc_b = (const float*)d_in[7];
    float* out = (float*)d_out;

    cudaFuncSetAttribute(k1_fused, cudaFuncAttributeMaxDynamicSharedMemorySize, SMEM1);
    cudaFuncSetAttribute(k2b_gru, cudaFuncAttributeMaxDynamicSharedMemorySize, SMEMB);

    k0_prepG<<<3, 192>>>(filt, w_ih);
    k0b_pack<<<24, 256>>>(b_ih, b_hh);
    k1_fused<<<8192, 256, SMEM1>>>(x);
    k2b_gru<<<256, 128, SMEMB>>>(w_hh, b_hh, fc_w);
    k3_fc<<<1, 256>>>(fc_b, out);
}

// round 17
// speedup vs baseline: 1.3660x; 1.1155x over previous
#include <cuda_runtime.h>
#include <cuda_fp16.h>
#include <math.h>
#include <stdint.h>

// ---------------------------------------------------------------------------
// STGNN R17 (= R16 + fp16 m16n8k16 for gi GEMM and GRU mma: half the HMMA
//            count; gi B-table fp16 -> L1-resident):
//  k0_prepG : Gcat[192][192] = stack_k(F_k @ w_ih^T)
//  k0b_pack : Gcat -> fp16 k16 B-fragment table + folded bias
//  k1_fused : sq -> Gram(3xtf32, d2' fused) -> bottom8(d2') parallel select
//             -> exp(8/row) -> sparse Cheb -> gi GEMM (fp16 m16n8k16)
//  k2b_gru  : tensor-core GRU (fp16 m16n8k16, MUFU.TANH gates), fused FC
//  k3_fc    : final reduce
// ---------------------------------------------------------------------------

#define DEV static __device__ __forceinline__
typedef unsigned long long ull;

// device scratch (no allocations allowed)
__device__ float g_gi[524288ull * 192];  // gi fragments: [(st*32+l)*24+nt][lane][4]
__device__ float g_G[192 * 192];         // Gcat
__device__ uint4 g_Gf16[12 * 12 * 32];   // fp16 B frags: [kc][ntp][lane]{4x.b32}
__device__ float g_bias[192];            // b_ih + b_hh (cols<128)
__device__ float g_part[1024];           // per-warp FC partials

DEV uint32_t to_tf32(float f) {
    uint32_t r;
    asm("cvt.rna.tf32.f32 %0, %1;" : "=r"(r) : "f"(f));
    return r;
}

// pack two f32 -> half2 {lo, hi}
DEV uint32_t f2h2(float lo, float hi) {
    uint32_t r;
    asm("cvt.rn.f16x2.f32 %0, %1, %2;" : "=r"(r) : "f"(hi), "f"(lo));
    return r;
}

DEV void mma8(float* c, const uint32_t* a, const uint32_t* b) {
    asm volatile(
        "mma.sync.aligned.m16n8k8.row.col.f32.tf32.tf32.f32 "
        "{%0,%1,%2,%3}, {%4,%5,%6,%7}, {%8,%9}, {%0,%1,%2,%3};"
        : "+f"(c[0]), "+f"(c[1]), "+f"(c[2]), "+f"(c[3])
        : "r"(a[0]), "r"(a[1]), "r"(a[2]), "r"(a[3]), "r"(b[0]), "r"(b[1]));
}

DEV void mma16(float* c, const uint32_t* a, uint32_t b0, uint32_t b1) {
    asm volatile(
        "mma.sync.aligned.m16n8k16.row.col.f32.f16.f16.f32 "
        "{%0,%1,%2,%3}, {%4,%5,%6,%7}, {%8,%9}, {%0,%1,%2,%3};"
        : "+f"(c[0]), "+f"(c[1]), "+f"(c[2]), "+f"(c[3])
        : "r"(a[0]), "r"(a[1]), "r"(a[2]), "r"(a[3]), "r"(b0), "r"(b1));
}

// keep 8 smallest, sorted ascending
DEV void ins8min(float (&lk)[8], float v) {
#pragma unroll
    for (int i = 0; i < 8; i++) {
        float lo = fminf(lk[i], v);
        v = fmaxf(lk[i], v);
        lk[i] = lo;
    }
}

// ---------------------------------------------------------------------------
// k0: Gcat[(k*64+f)][j] = sum_h F[k][f][h] * w_ih[j][h].  grid=3, block=192.
// ---------------------------------------------------------------------------
__global__ void __launch_bounds__(192) k0_prepG(const float* __restrict__ filters,
                                                const float* __restrict__ w_ih) {
    __shared__ float Fs[4096];
    const int k = blockIdx.x, j = threadIdx.x;
    for (int i = j; i < 4096; i += 192) Fs[i] = filters[k * 4096 + i];
    float w[64];
#pragma unroll
    for (int h = 0; h < 64; h++) w[h] = w_ih[j * 64 + h];
    __syncthreads();
    for (int f = 0; f < 64; f++) {
        float s = 0.f;
#pragma unroll
        for (int h = 0; h < 64; h++) s = fmaf(Fs[f * 64 + h], w[h], s);
        g_G[(k * 64 + f) * 192 + j] = s;
    }
}

// ---------------------------------------------------------------------------
// k0b: pack Gcat into fp16 m16n8k16 B-fragment table + bias. grid=12 (kc).
// For chunk kc (k rows kc*16..+16), ntp pair, lane (g2,tg2):
//   b0(nt) = {G[k0][n], G[k0+1][n]}, b1(nt) = {G[k0+8][n], G[k0+9][n]},
//   k0 = kc*16 + 2*tg2, n = nt*8+g2.  uint4 = {b0(2ntp),b1(2ntp),b0(2ntp+1),b1(2ntp+1)}
// ---------------------------------------------------------------------------
__global__ void __launch_bounds__(256) k0b_pack(const float* __restrict__ b_ih,
                                                const float* __restrict__ b_hh) {
    const int tid = threadIdx.x, kc = blockIdx.x;
    if (kc == 0 && tid < 192)
        g_bias[tid] = b_ih[tid] + (tid < 128 ? b_hh[tid] : 0.f);
    for (int i = tid; i < 384; i += 256) {
        int ntp = i >> 5, l2 = i & 31;
        int g2 = l2 >> 2, tg2 = l2 & 3;
        int k0 = kc * 16 + 2 * tg2;
        int n0 = (2 * ntp) * 8 + g2, n1 = n0 + 8;
        uint4 v;
        v.x = f2h2(g_G[k0 * 192 + n0], g_G[(k0 + 1) * 192 + n0]);
        v.y = f2h2(g_G[(k0 + 8) * 192 + n0], g_G[(k0 + 9) * 192 + n0]);
        v.z = f2h2(g_G[k0 * 192 + n1], g_G[(k0 + 1) * 192 + n1]);
        v.w = f2h2(g_G[(k0 + 8) * 192 + n1], g_G[(k0 + 9) * 192 + n1]);
        g_Gf16[(kc * 12 + ntp) * 32 + l2] = v;
    }
}

// ---------------------------------------------------------------------------
// k1_fused: grid=8192, block=256.  (R9 smem layout, 73216 B)
//   xsp 0..4352 (stride 68), adj 4352..8512 (stride 65; holds d2'), t1
//   8512..12864, t2 12864..17216, sq 17216..17280, val 17280..17792,
//   idx 17792..18304
// ---------------------------------------------------------------------------
#define SMEM1 (18304 * 4)

__global__ void __launch_bounds__(256) k1_fused(const float* __restrict__ x) {
    extern __shared__ __align__(16) float sm1[];
    float* xsp = sm1;
    float* adj = sm1 + 4352;
    float* t1  = sm1 + 8512;
    float* t2  = sm1 + 12864;
    float* sq  = sm1 + 17216;
    float* val = sm1 + 17280;
    int*   idx = (int*)(sm1 + 17792);

    const int m = blockIdx.x;
    const int b = m >> 5, l = m & 31;
    const int tid = threadIdx.x;
    const int wid = tid >> 5, lid = tid & 31;
    const int g = lid >> 2, tg = lid & 3;

    // load xf[n][f] -> xsp (stride 68)
    const float* xb = x + (size_t)b * 64 * 2048 + l * 64;
#pragma unroll
    for (int k = 0; k < 4; k++) {
        int v = tid + k * 256;
        int n = v >> 4, fo = (v & 15) << 2;
        *(float4*)(xsp + n * 68 + fo) = *(const float4*)(xb + (size_t)n * 2048 + fo);
    }
    __syncthreads();

    // sq[n] = sum_f x[n][f]^2  (4 threads/row + shfl reduce)
    {
        const int row = tid >> 2, seg = tid & 3;
        const float* xr = xsp + row * 68 + seg * 16;
        float s = 0.f;
#pragma unroll
        for (int e = 0; e < 16; e += 4) {
            float4 v = *(const float4*)(xr + e);
            s = fmaf(v.x, v.x, s);
            s = fmaf(v.y, v.y, s);
            s = fmaf(v.z, v.z, s);
            s = fmaf(v.w, v.w, s);
        }
        s += __shfl_xor_sync(0xffffffffu, s, 1);
        s += __shfl_xor_sync(0xffffffffu, s, 2);
        if (seg == 0) sq[row] = s;
    }
    __syncthreads();

    // Gram = xs @ xs^T via 3xtf32 split mma; d2' = max(d2,0) fused in epilogue
    {
        const int mt2 = wid >> 1, ntb = (wid & 1) * 4;
        float cacc[4][4];
#pragma unroll
        for (int t = 0; t < 4; t++)
#pragma unroll
            for (int q = 0; q < 4; q++) cacc[t][q] = 0.f;

#pragma unroll
        for (int kk = 0; kk < 8; kk++) {
            const int c0 = kk * 8 + tg, c1 = c0 + 4;
            const int r0 = mt2 * 16 + g, r1 = r0 + 8;
            float av[4] = {xsp[r0 * 68 + c0], xsp[r1 * 68 + c0],
                           xsp[r0 * 68 + c1], xsp[r1 * 68 + c1]};
            uint32_t ah[4], al[4];
#pragma unroll
            for (int q = 0; q < 4; q++) {
                ah[q] = to_tf32(av[q]);
                al[q] = to_tf32(av[q] - __uint_as_float(ah[q]));
            }
#pragma unroll
            for (int t = 0; t < 4; t++) {
                const int nr = (ntb + t) * 8 + g;
                float b0 = xsp[nr * 68 + c0], b1 = xsp[nr * 68 + c1];
                uint32_t bh[2], bl[2];
                bh[0] = to_tf32(b0); bl[0] = to_tf32(b0 - __uint_as_float(bh[0]));
                bh[1] = to_tf32(b1); bl[1] = to_tf32(b1 - __uint_as_float(bh[1]));
                mma8(cacc[t], ah, bl);
                mma8(cacc[t], al, bh);
                mma8(cacc[t], ah, bh);
            }
        }
        const int r0 = mt2 * 16 + g;
        const float sr0 = sq[r0], sr1 = sq[r0 + 8];
#pragma unroll
        for (int t = 0; t < 4; t++) {
            const int col = (ntb + t) * 8 + tg * 2;
            const float sc0 = sq[col], sc1 = sq[col + 1];
            adj[r0 * 65 + col]       = fmaxf(sr0 + sc0 - 2.f * cacc[t][0], 0.f);
            adj[r0 * 65 + col + 1]   = fmaxf(sr0 + sc1 - 2.f * cacc[t][1], 0.f);
            adj[(r0 + 8) * 65 + col] = fmaxf(sr1 + sc0 - 2.f * cacc[t][2], 0.f);
            adj[(r0 + 8) * 65 + col + 1] =
                fmaxf(sr1 + sc1 - 2.f * cacc[t][3], 0.f);
        }
    }
    __syncthreads();

    // bottom-8 of d2' per row (== top-8 of sim), parallel ordered selection.
    {
        const int row = tid >> 2, seg = tid & 3;
        const int j0 = seg * 16;
        float rv[16];
#pragma unroll
        for (int j = 0; j < 16; j++) rv[j] = adj[row * 65 + j0 + j];

        float lk[8];
#pragma unroll
        for (int i = 0; i < 8; i++) lk[i] = 3.4e38f;
#pragma unroll
        for (int j = 0; j < 16; j++) ins8min(lk, rv[j]);
#pragma unroll
        for (int o = 1; o <= 2; o <<= 1) {
            float ot[8];
#pragma unroll
            for (int i = 0; i < 8; i++)
                ot[i] = __shfl_xor_sync(0xffffffffu, lk[i], o);
#pragma unroll
            for (int i = 0; i < 8; i++) ins8min(lk, ot[i]);
        }
        const float thr = lk[7];

        int clt = 0, ceq = 0;
#pragma unroll
        for (int j = 0; j < 16; j++) {
            clt += (rv[j] < thr) ? 1 : 0;
            ceq += (rv[j] == thr) ? 1 : 0;
        }
        int ilt = clt, ieq = ceq;
#pragma unroll
        for (int o = 1; o < 4; o <<= 1) {
            int tl = __shfl_up_sync(0xffffffffu, ilt, o);
            int te = __shfl_up_sync(0xffffffffu, ieq, o);
            if (seg >= o) { ilt += tl; ieq += te; }
        }
        const int plt = ilt - clt, peq = ieq - ceq;
        const int tot_lt = __shfl_sync(0xffffffffu, ilt, lid | 3);
        const int rem = 8 - tot_lt;
        int tb = min(ceq, max(rem - peq, 0));
        int off = plt + min(peq, rem);
#pragma unroll
        for (int j = 0; j < 16; j++) {
            float v = rv[j];
            bool take = (v < thr);
            if (v == thr && tb > 0) { take = true; tb--; }
            if (take) {
                val[row * 8 + off] = __expf(-v);
                idx[row * 8 + off] = j0 + j;
                off++;
            }
        }
    }
    __syncwarp();

    // sparse Cheb: 4 threads per row, 16 f-cols each. lv/lj -> registers.
    const int row = tid >> 2, f0 = (tid & 3) << 4;
    float lv[8];
    int lj[8];
#pragma unroll
    for (int i = 0; i < 8; i++) { lv[i] = val[row * 8 + i]; lj[i] = idx[row * 8 + i]; }

    float4 a4[4];
#pragma unroll
    for (int q = 0; q < 4; q++) a4[q] = make_float4(0.f, 0.f, 0.f, 0.f);
#pragma unroll
    for (int i = 0; i < 8; i++) {
        float v = lv[i];
        const float4* xr = (const float4*)(xsp + lj[i] * 68 + f0);
#pragma unroll
        for (int q = 0; q < 4; q++) {
            float4 t = xr[q];
            a4[q].x = fmaf(v, t.x, a4[q].x);
            a4[q].y = fmaf(v, t.y, a4[q].y);
            a4[q].z = fmaf(v, t.z, a4[q].z);
            a4[q].w = fmaf(v, t.w, a4[q].w);
        }
    }
#pragma unroll
    for (int q = 0; q < 4; q++) *(float4*)(t1 + row * 68 + f0 + q * 4) = a4[q];
    __syncthreads();

    // Tx2 = 2*adj_sparse @ Tx1 - xs  -> t2
    float4 b4[4];
#pragma unroll
    for (int q = 0; q < 4; q++) b4[q] = make_float4(0.f, 0.f, 0.f, 0.f);
#pragma unroll
    for (int i = 0; i < 8; i++) {
        float v = lv[i];
        const float4* tr4 = (const float4*)(t1 + lj[i] * 68 + f0);
#pragma unroll
        for (int q = 0; q < 4; q++) {
            float4 t = tr4[q];
            b4[q].x = fmaf(v, t.x, b4[q].x);
            b4[q].y = fmaf(v, t.y, b4[q].y);
            b4[q].z = fmaf(v, t.z, b4[q].z);
            b4[q].w = fmaf(v, t.w, b4[q].w);
        }
    }
#pragma unroll
    for (int q = 0; q < 4; q++) {
        float4 xv = *(const float4*)(xsp + row * 68 + f0 + q * 4);
        float4 tn;
        tn.x = 2.f * b4[q].x - xv.x;
        tn.y = 2.f * b4[q].y - xv.y;
        tn.z = 2.f * b4[q].z - xv.z;
        tn.w = 2.f * b4[q].w - xv.w;
        *(float4*)(t2 + row * 68 + f0 + q * 4) = tn;
    }
    __syncthreads();

    // ---- gi GEMM: gi = [xsp|t1|t2] @ Gcat + bias, fp16 m16n8k16 ----
    const int mt = wid & 3, nh = wid >> 2;
    float acc[12][4];
#pragma unroll
    for (int nt = 0; nt < 12; nt++)
#pragma unroll
        for (int q = 0; q < 4; q++) acc[nt][q] = 0.f;

    const int r0 = mt * 16 + g;
#pragma unroll
    for (int kc = 0; kc < 12; kc++) {
        const float* Abuf = (kc < 4) ? xsp : ((kc < 8) ? t1 : t2);
        const int c0 = (kc & 3) * 16 + 2 * tg;
        uint32_t af[4];
        {
            float2 v0 = *(const float2*)(Abuf + r0 * 68 + c0);
            float2 v1 = *(const float2*)(Abuf + (r0 + 8) * 68 + c0);
            float2 v2 = *(const float2*)(Abuf + r0 * 68 + c0 + 8);
            float2 v3 = *(const float2*)(Abuf + (r0 + 8) * 68 + c0 + 8);
            af[0] = f2h2(v0.x, v0.y);
            af[1] = f2h2(v1.x, v1.y);
            af[2] = f2h2(v2.x, v2.y);
            af[3] = f2h2(v3.x, v3.y);
        }
        const uint4* Bf = g_Gf16 + ((size_t)kc * 12 + nh * 6) * 32 + lid;
#pragma unroll
        for (int p = 0; p < 6; p++) {
            uint4 bp = Bf[(size_t)p * 32];
            mma16(acc[p * 2], af, bp.x, bp.y);
            mma16(acc[p * 2 + 1], af, bp.z, bp.w);
        }
    }

    // epilogue: add bias, fragment-layout store
    const int st = b * 4 + mt;
    float4* dst = (float4*)g_gi + (((size_t)st * 32 + l) * 24 + nh * 12) * 32 + lid;
#pragma unroll
    for (int nt = 0; nt < 12; nt++) {
        const int ntg = nh * 12 + nt;
        float b0 = g_bias[ntg * 8 + tg * 2];
        float b1 = g_bias[ntg * 8 + tg * 2 + 1];
        dst[(size_t)nt * 32] = make_float4(acc[nt][0] + b0, acc[nt][1] + b1,
                                           acc[nt][2] + b0, acc[nt][3] + b1);
    }
}

// ---------------------------------------------------------------------------
// k2b: tensor-core GRU (fp16 m16n8k16) + fused FC. grid=256 x 128 thr.
// smem: pb4 1536 uint4 (24576 B) + hws 4*1088 floats (17408 B) = 41984 B
// ---------------------------------------------------------------------------
#define SMEMB (24576 + 17408)

DEV float sigf(float x) { return fmaf(0.5f, tanhf(0.5f * x), 0.5f); }

__global__ void __launch_bounds__(128) k2b_gru(const float* __restrict__ w_hh,
                                               const float* __restrict__ b_hh,
                                               const float* __restrict__ fc_w) {
    extern __shared__ __align__(16) float smb[];
    uint4* pb4 = (uint4*)smb;      // 1536 uint4
    float* hws = smb + 6144;       // 4*1088

    const int tid = threadIdx.x;
    const int ws = tid >> 5, lid = tid & 31;
    const int g = lid >> 2, tg = lid & 3;
    float* hw = hws + ws * 1088;

    // pack w_hh into fp16 k16 B-fragments
    for (int i = tid; i < 1536; i += 128) {
        int kt = i / 384, rem = i % 384;
        int ntp = rem >> 5, l2 = rem & 31;
        int g2 = l2 >> 2, tg2 = l2 & 3;
        int k0 = kt * 16 + 2 * tg2;
        int n0 = (2 * ntp) * 8 + g2, n1 = n0 + 8;
        uint4 v;
        v.x = f2h2(w_hh[n0 * 64 + k0], w_hh[n0 * 64 + k0 + 1]);
        v.y = f2h2(w_hh[n0 * 64 + k0 + 8], w_hh[n0 * 64 + k0 + 9]);
        v.z = f2h2(w_hh[n1 * 64 + k0], w_hh[n1 * 64 + k0 + 1]);
        v.w = f2h2(w_hh[n1 * 64 + k0 + 8], w_hh[n1 * 64 + k0 + 9]);
        pb4[i] = v;
    }
    for (int i = tid; i < 4 * 1088; i += 128) hws[i] = 0.f;
    __syncthreads();

    const int st = blockIdx.x * 4 + ws;

    float bhn[8][2];
#pragma unroll
    for (int jt = 0; jt < 8; jt++) {
        bhn[jt][0] = b_hh[128 + jt * 8 + tg * 2];
        bhn[jt][1] = b_hh[128 + jt * 8 + tg * 2 + 1];
    }
    float hold[8][4];
#pragma unroll
    for (int jt = 0; jt < 8; jt++)
#pragma unroll
        for (int q = 0; q < 4; q++) hold[jt][q] = 0.f;

    const int sl = lid >> 1, ch = (lid & 1) * 32;
    const int n_g = (st * 16 + sl) & 63;
    const float* fwrow = fc_w + n_g * 2048 + ch;
    float fcacc = 0.f;

    const float4* gibase = (const float4*)g_gi + (size_t)st * 32 * 24 * 32 + lid;

    for (int l = 0; l < 32; l++) {
        float acc[24][4];
        const float4* gl = gibase + (size_t)l * 24 * 32;
#pragma unroll
        for (int nt = 0; nt < 16; nt++) {
            float4 t = gl[(size_t)nt * 32];
            acc[nt][0] = t.x; acc[nt][1] = t.y; acc[nt][2] = t.z; acc[nt][3] = t.w;
        }
        float4 gin[8];
#pragma unroll
        for (int jt = 0; jt < 8; jt++) gin[jt] = gl[(size_t)(16 + jt) * 32];
#pragma unroll
        for (int jt = 0; jt < 8; jt++) {
            acc[16 + jt][0] = bhn[jt][0]; acc[16 + jt][1] = bhn[jt][1];
            acc[16 + jt][2] = bhn[jt][0]; acc[16 + jt][3] = bhn[jt][1];
        }
        // A-frags: h (fp32 smem) -> fp16 pairs; 4 k16 chunks
        uint32_t af[4][4];
#pragma unroll
        for (int kt = 0; kt < 4; kt++) {
            const int c0 = kt * 16 + 2 * tg;
            float2 v0 = *(const float2*)(hw + g * 68 + c0);
            float2 v1 = *(const float2*)(hw + (g + 8) * 68 + c0);
            float2 v2 = *(const float2*)(hw + g * 68 + c0 + 8);
            float2 v3 = *(const float2*)(hw + (g + 8) * 68 + c0 + 8);
            af[kt][0] = f2h2(v0.x, v0.y);
            af[kt][1] = f2h2(v1.x, v1.y);
            af[kt][2] = f2h2(v2.x, v2.y);
            af[kt][3] = f2h2(v3.x, v3.y);
        }
#pragma unroll
        for (int kt = 0; kt < 4; kt++) {
#pragma unroll
            for (int ntp = 0; ntp < 12; ntp++) {
                uint4 bp = pb4[(kt * 12 + ntp) * 32 + lid];
                mma16(acc[ntp * 2], af[kt], bp.x, bp.y);
                mma16(acc[ntp * 2 + 1], af[kt], bp.z, bp.w);
            }
        }
        float hnew[8][4];
#pragma unroll
        for (int jt = 0; jt < 8; jt++) {
            float gq[4] = {gin[jt].x, gin[jt].y, gin[jt].z, gin[jt].w};
#pragma unroll
            for (int q = 0; q < 4; q++) {
                float r = sigf(acc[jt][q]);
                float z = sigf(acc[jt + 8][q]);
                float n = tanhf(gq[q] + r * acc[jt + 16][q]);
                float hv = (1.f - z) * n + z * hold[jt][q];
                hnew[jt][q] = hv;
                hold[jt][q] = hv;
            }
        }
        __syncwarp();
#pragma unroll
        for (int jt = 0; jt < 8; jt++) {
            *(float2*)(hw + g * 68 + jt * 8 + tg * 2) =
                make_float2(hnew[jt][0], hnew[jt][1]);
            *(float2*)(hw + (g + 8) * 68 + jt * 8 + tg * 2) =
                make_float2(hnew[jt][2], hnew[jt][3]);
        }
        __syncwarp();
        const float* hrow = hw + sl * 68 + ch;
        const float* fw = fwrow + l * 64;
#pragma unroll
        for (int u = 0; u < 8; u++) {
            float4 hh = *(const float4*)(hrow + u * 4);
            float4 wf = *(const float4*)(fw + u * 4);
            fcacc += hh.x * wf.x + hh.y * wf.y + hh.z * wf.z + hh.w * wf.w;
        }
    }

#pragma unroll
    for (int o = 16; o > 0; o >>= 1)
        fcacc += __shfl_down_sync(0xffffffffu, fcacc, o);
    if (lid == 0) g_part[blockIdx.x * 4 + ws] = fcacc;
}

// ---------------------------------------------------------------------------
__global__ void k3_fc(const float* __restrict__ fc_b, float* __restrict__ out) {
    int b = threadIdx.x;
    float s = fc_b[0];
#pragma unroll
    for (int k = 0; k < 4; k++) s += g_part[b * 4 + k];
    out[b] = s;
}

// ---------------------------------------------------------------------------
extern "C" void kernel_launch(void* const* d_in, const int* in_sizes, int n_in,
                              void* d_out, int out_size) {
    const float* x    = (const float*)d_in[0];
    const float* filt = (const float*)d_in[1];
    const float* w_ih = (const float*)d_in[2];
    const float* w_hh = (const float*)d_in[3];
    const float* b_ih = (const float*)d_in[4];
    const float* b_hh = (const float*)d_in[5];
    const float* fc_w = (const float*)d_in[6];
    const float* fc_b = (const float*)d_in[7];
    float* out = (float*)d_out;

    cudaFuncSetAttribute(k1_fused, cudaFuncAttributeMaxDynamicSharedMemorySize, SMEM1);
    cudaFuncSetAttribute(k2b_gru, cudaFuncAttributeMaxDynamicSharedMemorySize, SMEMB);

    k0_prepG<<<3, 192>>>(filt, w_ih);
    k0b_pack<<<12, 256>>>(b_ih, b_hh);
    k1_fused<<<8192, 256, SMEM1>>>(x);
    k2b_gru<<<256, 128, SMEMB>>>(w_hh, b_hh, fc_w);
    k3_fc<<<1, 256>>>(fc_b, out);
}